// round 4
// baseline (speedup 1.0000x reference)
#include <cuda_runtime.h>
#include <cstdint>

#define N_QUBITS 16
#define DIM 65536
#define BATCH 128

typedef unsigned long long ull;

// Scratch state buffers (device globals: allocation-free rule). float4-aligned.
__device__ float4 g_state0[BATCH * DIM / 2];
__device__ float4 g_state1[BATCH * DIM / 2];
__device__ float  g_partial[BATCH * 16 * 16];   // [b][loGroup][q]

// ---------------------------------------------------------------------------
// Packed f32x2 helpers
__device__ __forceinline__ ull pk(float lo, float hi) {
    ull r; asm("mov.b64 %0, {%1, %2};" : "=l"(r) : "f"(lo), "f"(hi)); return r;
}
__device__ __forceinline__ void unpk(ull p, float& lo, float& hi) {
    asm("mov.b64 {%0, %1}, %2;" : "=f"(lo), "=f"(hi) : "l"(p));
}
__device__ __forceinline__ ull f2fma(ull a, ull b, ull c) {
    ull d; asm("fma.rn.f32x2 %0, %1, %2, %3;" : "=l"(d) : "l"(a), "l"(b), "l"(c)); return d;
}
__device__ __forceinline__ ull f2mul(ull a, ull b) {
    ull d; asm("mul.rn.f32x2 %0, %1, %2;" : "=l"(d) : "l"(a), "l"(b)); return d;
}
__device__ __forceinline__ ull shfl_xor_u64(ull v, int m) {
    float lo, hi; unpk(v, lo, hi);
    lo = __shfl_xor_sync(0xffffffffu, lo, m);
    hi = __shfl_xor_sync(0xffffffffu, hi, m);
    return pk(lo, hi);
}

// ---------------------------------------------------------------------------
// CNOT-ring permutation sigma: new index j from old index i.
__device__ __forceinline__ int sigma16(int i) {
    int t = i;
    t ^= t >> 1; t ^= t >> 2; t ^= t >> 4; t ^= t >> 8;
    int b15 = (t ^ (i >> 15)) & 1;
    return (t & 0x7FFF) | (b15 << 15);
}

// ---------------------------------------------------------------------------
// Gate construction: G = Rot(phi,theta,omega) @ RY(x)   (complex 2x2)
// g[8] = {G00r,G00i, G01r,G01i, G10r,G10i, G11r,G11i}
__device__ void compute_gate(const float* __restrict__ x,
                             const float* __restrict__ w,
                             int b, int l, int q, float g[8]) {
    float xv  = x[(b * 4 + l) * 16 + q];
    const float* wp = w + (l * 16 + q) * 3;
    float phi = wp[0], th = wp[1], om = wp[2];
    float ct, st, cr, sr, sp, cp, sm, cm;
    sincosf(0.5f * th, &st, &ct);
    sincosf(0.5f * xv, &sr, &cr);
    sincosf(0.5f * (phi + om), &sp, &cp);
    sincosf(0.5f * (phi - om), &sm, &cm);
    float m00r =  cp * ct, m00i = -sp * ct;
    float m01r = -cm * st, m01i = -sm * st;
    float m10r =  cm * st, m10i = -sm * st;
    float m11r =  cp * ct, m11i =  sp * ct;
    g[0] =  m00r * cr + m01r * sr;  g[1] =  m00i * cr + m01i * sr;
    g[2] = -m00r * sr + m01r * cr;  g[3] = -m00i * sr + m01i * cr;
    g[4] =  m10r * cr + m11r * sr;  g[5] =  m10i * cr + m11i * sr;
    g[6] = -m10r * sr + m11r * cr;  g[7] = -m10i * sr + m11i * cr;
}

// Packed gate table layout, 12 u64 broadcasts per gate:
//  [0]=(g0)  [1]=(-g1) [2]=(g1)  [3]=(g2)  [4]=(-g3) [5]=(g3)
//  [6]=(g6)  [7]=(-g7) [8]=(g7)  [9]=(g4)  [10]=(-g5) [11]=(g5)
__device__ __forceinline__ void fill_gate_tables(const float g[8], float* gsc, ull* gp) {
    #pragma unroll
    for (int k = 0; k < 8; k++) gsc[k] = g[k];
    gp[0]  = pk(g[0], g[0]);   gp[1]  = pk(-g[1], -g[1]); gp[2]  = pk(g[1], g[1]);
    gp[3]  = pk(g[2], g[2]);   gp[4]  = pk(-g[3], -g[3]); gp[5]  = pk(g[3], g[3]);
    gp[6]  = pk(g[6], g[6]);   gp[7]  = pk(-g[7], -g[7]); gp[8]  = pk(g[7], g[7]);
    gp[9]  = pk(g[4], g[4]);   gp[10] = pk(-g[5], -g[5]); gp[11] = pk(g[5], g[5]);
}

// Scalar complex gate on pair (A,B)
__device__ __forceinline__ void cgate(float2& A, float2& B, const float* __restrict__ g) {
    float ar = A.x, ai = A.y, br = B.x, bi = B.y;
    A.x = g[0]*ar - g[1]*ai + g[2]*br - g[3]*bi;
    A.y = g[0]*ai + g[1]*ar + g[2]*bi + g[3]*br;
    B.x = g[4]*ar - g[5]*ai + g[6]*br - g[7]*bi;
    B.y = g[4]*ai + g[5]*ar + g[6]*bi + g[7]*br;
}

// Packed register-pair gate: packs (Are,Aim) pair with (Bre,Bim), table row L.
__device__ __forceinline__ void regGate(ull& Are, ull& Aim, ull& Bre, ull& Bim,
                                        const ull* __restrict__ L) {
    ull nAre = f2fma(L[0], Are, f2fma(L[1],  Aim, f2fma(L[3], Bre, f2mul(L[4],  Bim))));
    ull nAim = f2fma(L[0], Aim, f2fma(L[2],  Are, f2fma(L[3], Bim, f2mul(L[5],  Bre))));
    ull nBre = f2fma(L[9], Are, f2fma(L[10], Aim, f2fma(L[6], Bre, f2mul(L[7],  Bim))));
    ull nBim = f2fma(L[9], Aim, f2fma(L[11], Are, f2fma(L[6], Bim, f2mul(L[8],  Bre))));
    Are = nAre; Aim = nAim; Bre = nBre; Bim = nBim;
}

// P[0..3] = Pre packs, P[4..7] = Pim packs (pack idx = 2 "register" bits).
// Applies: regLoGate on pack-bit0, regHiGate on pack-bit1, then 5 lane-shuffle
// gates (lane bit s -> gate index s+shufBase).
__device__ __forceinline__ void applyPacked(ull P[8], const ull* __restrict__ gpk,
                                            int shufBase, int regLoGate, int regHiGate,
                                            int lane) {
    {
        const ull* L = gpk + regLoGate * 12;
        regGate(P[0], P[4], P[1], P[5], L);
        regGate(P[2], P[6], P[3], P[7], L);
    }
    {
        const ull* L = gpk + regHiGate * 12;
        regGate(P[0], P[4], P[2], P[6], L);
        regGate(P[1], P[5], P[3], P[7], L);
    }
    #pragma unroll
    for (int s = 0; s < 5; s++) {
        int bit = (lane >> s) & 1;
        const ull* C = gpk + (s + shufBase) * 12 + 6 * bit;
        ull c0 = C[0], c1 = C[1], c2 = C[2], c3 = C[3], c4 = C[4], c5 = C[5];
        #pragma unroll
        for (int k = 0; k < 4; k++) {
            ull pre = shfl_xor_u64(P[k],     1 << s);
            ull pim = shfl_xor_u64(P[k + 4], 1 << s);
            ull nre = f2fma(c0, P[k],     f2fma(c1, P[k + 4], f2fma(c3, pre, f2mul(c4, pim))));
            ull nim = f2fma(c0, P[k + 4], f2fma(c2, P[k],     f2fma(c3, pim, f2mul(c5, pre))));
            P[k] = nre; P[k + 4] = nim;
        }
    }
}

// ---------------------------------------------------------------------------
// K1: layer 0 from |0>: product state, then CNOT-ring scatter. Write-only.
__global__ __launch_bounds__(256)
void k_init(const float* __restrict__ x, const float* __restrict__ w,
            float2* __restrict__ st) {
    int b = blockIdx.x, tid = threadIdx.x;
    __shared__ float  gcol[16][4];
    __shared__ float2 loP[256], hiP[256];
    if (tid < 16) {
        float g[8];
        compute_gate(x, w, b, 0, 15 - tid, g);
        gcol[tid][0] = g[0]; gcol[tid][1] = g[1];
        gcol[tid][2] = g[4]; gcol[tid][3] = g[5];
    }
    __syncthreads();
    {
        float lr = 1.f, li = 0.f, hr = 1.f, hi = 0.f;
        #pragma unroll
        for (int p = 0; p < 8; p++) {
            int bit = (tid >> p) & 1;
            float ar = gcol[p][2 * bit], ai = gcol[p][2 * bit + 1];
            float nr = lr * ar - li * ai, ni = lr * ai + li * ar;
            lr = nr; li = ni;
            float br = gcol[p + 8][2 * bit], bi = gcol[p + 8][2 * bit + 1];
            nr = hr * br - hi * bi; ni = hr * bi + hi * br;
            hr = nr; hi = ni;
        }
        loP[tid] = make_float2(lr, li);
        hiP[tid] = make_float2(hr, hi);
    }
    __syncthreads();
    float2* base = st + (size_t)b * DIM;
    for (int it = 0; it < 256; it++) {
        int i = it * 256 + tid;
        float2 h = hiP[it], lo = loP[tid];
        float2 amp = make_float2(h.x * lo.x - h.y * lo.y,
                                 h.x * lo.y + h.y * lo.x);
        base[sigma16(i)] = amp;
    }
}

// ---------------------------------------------------------------------------
// KA: gates on index bits 0..7 (qubits 15..8). In-place, f32x2 packed.
// Thread r-chunk mapping: amp = hi*256 + r*64 + lane*2 + h
//   bit0=h (scalar gate 0), bits1..5=lane (shuffle gates 1..5),
//   bits6,7=r (packed reg gates 6,7)
__global__ __launch_bounds__(256)
void k_low(const float* __restrict__ x, const float* __restrict__ w,
           int layer, float4* __restrict__ st4) {
    int b = blockIdx.y, tid = threadIdx.x;
    int wid = tid >> 5, lane = tid & 31;
    __shared__ ull   gpk[96];
    __shared__ float gsc[8][8];
    if (tid < 8) {
        float g[8];
        compute_gate(x, w, b, layer, 15 - tid, g);
        fill_gate_tables(g, gsc[tid], gpk + tid * 12);
    }
    __syncthreads();
    int hi = blockIdx.x * 8 + wid;                       // 0..255
    float4* base = st4 + (size_t)b * (DIM / 2) + hi * 128;
    float4 v[4];
    #pragma unroll
    for (int r = 0; r < 4; r++) v[r] = base[r * 32 + lane];
    // scalar gate on bit0 (intra-float4 amp pair)
    #pragma unroll
    for (int r = 0; r < 4; r++) {
        float2 A = make_float2(v[r].x, v[r].y), B = make_float2(v[r].z, v[r].w);
        cgate(A, B, gsc[0]);
        v[r] = make_float4(A.x, A.y, B.x, B.y);
    }
    ull P[8];
    #pragma unroll
    for (int r = 0; r < 4; r++) { P[r] = pk(v[r].x, v[r].z); P[r + 4] = pk(v[r].y, v[r].w); }
    applyPacked(P, gpk, /*shufBase=*/1, /*regLo=*/6, /*regHi=*/7, lane);
    #pragma unroll
    for (int r = 0; r < 4; r++) {
        float re0, re1, im0, im1;
        unpk(P[r], re0, re1); unpk(P[r + 4], im0, im1);
        base[r * 32 + lane] = make_float4(re0, im0, re1, im1);
    }
}

// ---------------------------------------------------------------------------
// KB: gates on index bits 8..15 (qubits 7..0) via smem transpose tile,
// fused CNOT-ring scatter (non-final) or fused sign-weighted reduction (final).
// hi-index mapping: bits0..4=lane (shuffle gates 0..4), bits5,6=pack idx
// (reg gates 5,6), bit7=pack half (scalar gate 7).
template <bool FINAL>
__global__ __launch_bounds__(256)
void k_high(const float* __restrict__ x, const float* __restrict__ w,
            int layer, const float2* __restrict__ in,
            float2* __restrict__ outst, float* __restrict__ part) {
    int b = blockIdx.y, logrp = blockIdx.x;
    int tid = threadIdx.x, wid = tid >> 5, lane = tid & 31;
    __shared__ ull    gpk[96];
    __shared__ float  gsc[8][8];
    __shared__ float2 tile[16][257];
    __shared__ float  wsum[8][16];

    if (tid < 8) {
        float g[8];
        compute_gate(x, w, b, layer, 7 - tid, g);        // hi-bit p -> qubit 7-p
        fill_gate_tables(g, gsc[tid], gpk + tid * 12);
    }
    __syncthreads();

    const float2* ibase = in + (size_t)b * DIM + logrp * 16;
    #pragma unroll 4
    for (int it = 0; it < 16; it++) {
        int hi = it * 16 + wid * 2 + (lane >> 4);
        int lo = lane & 15;
        tile[lo][hi] = ibase[hi * 256 + lo];
    }
    __syncthreads();

    #pragma unroll
    for (int sub = 0; sub < 2; sub++) {
        int lo = wid * 2 + sub;
        float2 v[8];
        #pragma unroll
        for (int r = 0; r < 8; r++) v[r] = tile[lo][r * 32 + lane];
        // scalar gate on bit7 (pairs r, r+4)
        #pragma unroll
        for (int r = 0; r < 4; r++) cgate(v[r], v[r + 4], gsc[7]);
        ull P[8];
        #pragma unroll
        for (int p = 0; p < 4; p++) { P[p] = pk(v[p].x, v[p + 4].x); P[p + 4] = pk(v[p].y, v[p + 4].y); }
        applyPacked(P, gpk, /*shufBase=*/0, /*regLo=*/5, /*regHi=*/6, lane);
        #pragma unroll
        for (int p = 0; p < 4; p++) {
            float a, c, bb, d;
            unpk(P[p], a, c); unpk(P[p + 4], bb, d);
            v[p]     = make_float2(a, bb);
            v[p + 4] = make_float2(c, d);
        }
        #pragma unroll
        for (int r = 0; r < 8; r++) tile[lo][r * 32 + lane] = v[r];
    }
    __syncthreads();

    if (!FINAL) {
        float2* obase = outst + (size_t)b * DIM;
        #pragma unroll 4
        for (int it = 0; it < 16; it++) {
            int hi = it * 16 + wid * 2 + (lane >> 4);
            int lo = lane & 15;
            float2 val = tile[lo][hi];
            int i = hi * 256 + logrp * 16 + lo;
            obase[sigma16(i)] = val;
        }
    } else {
        float acc[16];
        #pragma unroll
        for (int q = 0; q < 16; q++) acc[q] = 0.f;
        for (int it = 0; it < 16; it++) {
            int hi = it * 16 + wid * 2 + (lane >> 4);
            int lo = lane & 15;
            float2 val = tile[lo][hi];
            int i = hi * 256 + logrp * 16 + lo;
            int j = sigma16(i);
            float p = val.x * val.x + val.y * val.y;
            #pragma unroll
            for (int q = 0; q < 16; q++) {
                unsigned sgn = ((unsigned)(j >> (15 - q)) & 1u) << 31;
                acc[q] += __int_as_float(__float_as_int(p) ^ sgn);
            }
        }
        #pragma unroll
        for (int q = 0; q < 16; q++) {
            float a = acc[q];
            #pragma unroll
            for (int o = 16; o; o >>= 1) a += __shfl_down_sync(0xffffffffu, a, o);
            if (lane == 0) wsum[wid][q] = a;
        }
        __syncthreads();
        if (tid < 16) {
            float s = 0.f;
            #pragma unroll
            for (int ww = 0; ww < 8; ww++) s += wsum[ww][tid];
            part[(b * 16 + logrp) * 16 + tid] = s;
        }
    }
}

// Final deterministic reduction of partials -> out[b][q]
__global__ __launch_bounds__(256)
void k_reduce(const float* __restrict__ part, float* __restrict__ out) {
    int idx = blockIdx.x * 256 + threadIdx.x;          // < 2048
    int b = idx >> 4, q = idx & 15;
    float s = 0.f;
    #pragma unroll
    for (int gp = 0; gp < 16; gp++) s += part[(b * 16 + gp) * 16 + q];
    out[idx] = s;
}

// ---------------------------------------------------------------------------
extern "C" void kernel_launch(void* const* d_in, const int* in_sizes, int n_in,
                              void* d_out, int out_size) {
    const float* x = (const float*)d_in[0];
    const float* w = (const float*)d_in[1];
    if (n_in >= 2 && in_sizes[0] == 192) { const float* t = x; x = w; w = t; }
    float* out = (float*)d_out;

    float4 *s0, *s1; float* part;
    cudaGetSymbolAddress((void**)&s0, g_state0);
    cudaGetSymbolAddress((void**)&s1, g_state1);
    cudaGetSymbolAddress((void**)&part, g_partial);

    k_init<<<BATCH, 256>>>(x, w, (float2*)s0);

    k_low <<<dim3(32, BATCH), 256>>>(x, w, 1, s0);
    k_high<false><<<dim3(16, BATCH), 256>>>(x, w, 1, (const float2*)s0, (float2*)s1, nullptr);

    k_low <<<dim3(32, BATCH), 256>>>(x, w, 2, s1);
    k_high<false><<<dim3(16, BATCH), 256>>>(x, w, 2, (const float2*)s1, (float2*)s0, nullptr);

    k_low <<<dim3(32, BATCH), 256>>>(x, w, 3, s0);
    k_high<true> <<<dim3(16, BATCH), 256>>>(x, w, 3, (const float2*)s0, nullptr, part);

    k_reduce<<<8, 256>>>(part, out);
}

// round 5
// speedup vs baseline: 1.1933x; 1.1933x over previous
#include <cuda_runtime.h>
#include <cstdint>

#define N_QUBITS 16
#define DIM 65536
#define BATCH 128

// Scratch state buffers (device globals: allocation-free rule).
__device__ float2 g_state0[BATCH * DIM];
__device__ float2 g_state1[BATCH * DIM];
__device__ float  g_partial[BATCH * 16 * 16];   // [b][loGroup][q]

// ---------------------------------------------------------------------------
__device__ __forceinline__ float2 cmul(float2 a, float2 b) {
    return make_float2(a.x * b.x - a.y * b.y, a.x * b.y + a.y * b.x);
}

// CNOT-ring permutation sigma: new index j from old index i.
__device__ __forceinline__ int sigma16(int i) {
    int t = i;
    t ^= t >> 1; t ^= t >> 2; t ^= t >> 4; t ^= t >> 8;
    int b15 = (t ^ (i >> 15)) & 1;
    return (t & 0x7FFF) | (b15 << 15);
}

// ---------------------------------------------------------------------------
// First column (and implicitly structure) of G = Rot(phi,theta,omega) @ RY(x).
// Returns a = G00 = (g0,g1), b = G10 = (g4,g5).  G is SU(2):
// G = [[a, -conj(b)], [b, conj(a)]].
__device__ void gate_col(const float* __restrict__ x,
                         const float* __restrict__ w,
                         int b, int l, int q,
                         float& g0, float& g1, float& g4, float& g5) {
    float xv  = x[(b * 4 + l) * 16 + q];
    const float* wp = w + (l * 16 + q) * 3;
    float phi = wp[0], th = wp[1], om = wp[2];
    float ct, st, cr, sr, sp, cp, sm, cm;
    sincosf(0.5f * th, &st, &ct);
    sincosf(0.5f * xv, &sr, &cr);
    sincosf(0.5f * (phi + om), &sp, &cp);
    sincosf(0.5f * (phi - om), &sm, &cm);
    float m00r =  cp * ct, m00i = -sp * ct;
    float m01r = -cm * st, m01i = -sm * st;
    float m10r =  cm * st, m10i = -sm * st;
    float m11r =  cp * ct, m11i =  sp * ct;
    g0 = m00r * cr + m01r * sr;  g1 = m00i * cr + m01i * sr;
    g4 = m10r * cr + m11r * sr;  g5 = m10i * cr + m11i * sr;
}

// ZYZ-style decomposition: G = diag(p0, conj(p0)) @ [[c,-s],[s,c]] @ diag(q0, conj(q0))
// with c = |a|, s = |b|, q0 = e^{i(au+av)/2}, p0 = e^{i(au-av)/2},
// au = arg(a), av = arg(b).  (Check: p0*q0*c = a, conj(p0)*q0*s = b.)
__device__ void gate_decomp(const float* __restrict__ x,
                            const float* __restrict__ w,
                            int b, int l, int q,
                            float2& cs, float2& q0, float2& p0) {
    float g0, g1, g4, g5;
    gate_col(x, w, b, l, q, g0, g1, g4, g5);
    float ca = sqrtf(g0 * g0 + g1 * g1);
    float sb = sqrtf(g4 * g4 + g5 * g5);
    float au = atan2f(g1, g0);
    float av = atan2f(g5, g4);
    float s1, c1, s2, c2;
    sincosf(0.5f * (au + av), &s1, &c1);
    sincosf(0.5f * (au - av), &s2, &c2);
    cs = make_float2(ca, sb);
    q0 = make_float2(c1, s1);
    p0 = make_float2(c2, s2);
}

// ---------------------------------------------------------------------------
// Real-rotation butterfly network on 8 amps/thread:
//   lane bits 0..4 -> gates gcs[0..4] (shfl), reg bits -> gates gcs[5..7].
__device__ __forceinline__ void apply8_real(float2 v[8],
                                            const float2* __restrict__ gcs,
                                            int lane) {
    #pragma unroll
    for (int pb = 0; pb < 3; pb++) {
        int m = 1 << pb;
        float2 cspair = gcs[5 + pb];
        float c = cspair.x, s = cspair.y;
        #pragma unroll
        for (int r = 0; r < 8; r++)
            if (!(r & m)) {
                float2 A = v[r], B = v[r + m];
                v[r]     = make_float2(c * A.x - s * B.x, c * A.y - s * B.y);
                v[r + m] = make_float2(s * A.x + c * B.x, s * A.y + c * B.y);
            }
    }
    #pragma unroll
    for (int p = 0; p < 5; p++) {
        float2 cspair = gcs[p];
        float c = cspair.x;
        float s = ((lane >> p) & 1) ? cspair.y : -cspair.y;
        #pragma unroll
        for (int r = 0; r < 8; r++) {
            float px = __shfl_xor_sync(0xffffffffu, v[r].x, 1 << p);
            float py = __shfl_xor_sync(0xffffffffu, v[r].y, 1 << p);
            v[r].x = c * v[r].x + s * px;
            v[r].y = c * v[r].y + s * py;
        }
    }
}

// ---------------------------------------------------------------------------
// K1: layer 0 from |0>: product state (full G column), then CNOT-ring scatter.
__global__ __launch_bounds__(256)
void k_init(const float* __restrict__ x, const float* __restrict__ w,
            float2* __restrict__ st) {
    int b = blockIdx.x, tid = threadIdx.x;
    __shared__ float  gcol[16][4];
    __shared__ float2 loP[256], hiP[256];
    if (tid < 16) {
        float g0, g1, g4, g5;
        compute_gate_marker:;
        gate_col(x, w, b, 0, 15 - tid, g0, g1, g4, g5);
        gcol[tid][0] = g0; gcol[tid][1] = g1;
        gcol[tid][2] = g4; gcol[tid][3] = g5;
    }
    __syncthreads();
    {
        float lr = 1.f, li = 0.f, hr = 1.f, hi = 0.f;
        #pragma unroll
        for (int p = 0; p < 8; p++) {
            int bit = (tid >> p) & 1;
            float ar = gcol[p][2 * bit], ai = gcol[p][2 * bit + 1];
            float nr = lr * ar - li * ai, ni = lr * ai + li * ar;
            lr = nr; li = ni;
            float br = gcol[p + 8][2 * bit], bi = gcol[p + 8][2 * bit + 1];
            nr = hr * br - hi * bi; ni = hr * bi + hi * br;
            hr = nr; hi = ni;
        }
        loP[tid] = make_float2(lr, li);
        hiP[tid] = make_float2(hr, hi);
    }
    __syncthreads();
    float2* base = st + (size_t)b * DIM;
    for (int it = 0; it < 256; it++) {
        int i = it * 256 + tid;
        float2 h = hiP[it], lo = loP[tid];
        base[sigma16(i)] = cmul(h, lo);
    }
}

// ---------------------------------------------------------------------------
// KA: D2(layer) diagonal + real rotations on index bits 0..7 (qubits 15..8).
// In-place. amp_local = r*32 + lane; bits 0-4 lane, 5-7 r. hi fixed per warp.
__global__ __launch_bounds__(256)
void k_low(const float* __restrict__ x, const float* __restrict__ w,
           int layer, float2* __restrict__ st) {
    int b = blockIdx.y, tid = threadIdx.x;
    int wid = tid >> 5, lane = tid & 31;
    __shared__ float2 gcs[8], qlo[8], qhi[8], d2lo[256];

    if (tid < 16) {
        float2 cs, q0, p0;
        gate_decomp(x, w, b, layer, 15 - tid, cs, q0, p0);
        if (tid < 8) { gcs[tid] = cs; qlo[tid] = q0; }
        else         { qhi[tid - 8] = q0; }
    }
    __syncthreads();
    {   // d2lo[m] = prod_p (bit_p(m) ? conj(q0_p) : q0_p), bits 0..7
        float2 acc = make_float2(1.f, 0.f);
        #pragma unroll
        for (int p = 0; p < 8; p++) {
            float2 ph = qlo[p];
            if ((tid >> p) & 1) ph.y = -ph.y;
            acc = cmul(acc, ph);
        }
        d2lo[tid] = acc;
    }
    int hi = blockIdx.x * 8 + wid;                  // 0..255
    float2 dh = make_float2(1.f, 0.f);              // d2hi(hi), bits 8..15
    #pragma unroll
    for (int p = 0; p < 8; p++) {
        float2 ph = qhi[p];
        if ((hi >> p) & 1) ph.y = -ph.y;
        dh = cmul(dh, ph);
    }
    __syncthreads();

    float2* base = st + (size_t)b * DIM + hi * 256;
    float2 v[8];
    #pragma unroll
    for (int r = 0; r < 8; r++) v[r] = base[r * 32 + lane];
    // apply D2 = dh * d2lo[local]
    #pragma unroll
    for (int r = 0; r < 8; r++) {
        float2 d = cmul(dh, d2lo[r * 32 + lane]);
        v[r] = cmul(v[r], d);
    }
    apply8_real(v, gcs, lane);
    #pragma unroll
    for (int r = 0; r < 8; r++) base[r * 32 + lane] = v[r];
}

// ---------------------------------------------------------------------------
// KB: real rotations on index bits 8..15 (qubits 7..0) via smem transpose,
// then D1(layer) diagonal (skipped if FINAL), then fused CNOT scatter or
// fused sign-weighted readout.
// hi bits 0-4 lane (gates 0..4), bits 5-7 reg (gates 5..7); lo fixed per warp-sub.
template <bool FINAL>
__global__ __launch_bounds__(256)
void k_high(const float* __restrict__ x, const float* __restrict__ w,
            int layer, const float2* __restrict__ in,
            float2* __restrict__ outst, float* __restrict__ part) {
    int b = blockIdx.y, logrp = blockIdx.x;
    int tid = threadIdx.x, wid = tid >> 5, lane = tid & 31;
    __shared__ float2 gcs[8], php[8], plp[8];
    __shared__ float2 d1hi[256], d1lo[16];
    __shared__ float2 tile[16][257];
    __shared__ float  wsum[8][16];

    if (tid < 8) {
        float2 cs, q0, p0;
        gate_decomp(x, w, b, layer, 7 - tid, cs, q0, p0);   // hi-bit p -> qubit 7-p
        gcs[tid] = cs; php[tid] = p0;
    } else if (!FINAL && tid < 16) {
        float2 cs, q0, p0;
        gate_decomp(x, w, b, layer, 15 - (tid - 8), cs, q0, p0); // lo-bit gates
        plp[tid - 8] = p0;
    }
    __syncthreads();

    if (!FINAL) {
        float2 acc = make_float2(1.f, 0.f);
        #pragma unroll
        for (int p = 0; p < 8; p++) {
            float2 ph = php[p];
            if ((tid >> p) & 1) ph.y = -ph.y;
            acc = cmul(acc, ph);
        }
        d1hi[tid] = acc;
        if (tid < 16) {
            int lo = logrp * 16 + tid;
            float2 a2 = make_float2(1.f, 0.f);
            #pragma unroll
            for (int p = 0; p < 8; p++) {
                float2 ph = plp[p];
                if ((lo >> p) & 1) ph.y = -ph.y;
                a2 = cmul(a2, ph);
            }
            d1lo[tid] = a2;
        }
    }

    const float2* ibase = in + (size_t)b * DIM + logrp * 16;
    #pragma unroll 4
    for (int it = 0; it < 16; it++) {
        int hi = it * 16 + wid * 2 + (lane >> 4);
        int lo = lane & 15;
        tile[lo][hi] = ibase[hi * 256 + lo];
    }
    __syncthreads();

    #pragma unroll
    for (int sub = 0; sub < 2; sub++) {
        int lo = wid * 2 + sub;
        float2 v[8];
        #pragma unroll
        for (int r = 0; r < 8; r++) v[r] = tile[lo][r * 32 + lane];
        apply8_real(v, gcs, lane);
        if (!FINAL) {
            float2 dl = d1lo[lo];
            #pragma unroll
            for (int r = 0; r < 8; r++) {
                float2 d = cmul(d1hi[r * 32 + lane], dl);
                v[r] = cmul(v[r], d);
            }
        }
        #pragma unroll
        for (int r = 0; r < 8; r++) tile[lo][r * 32 + lane] = v[r];
    }
    __syncthreads();

    if (!FINAL) {
        float2* obase = outst + (size_t)b * DIM;
        #pragma unroll 4
        for (int it = 0; it < 16; it++) {
            int hi = it * 16 + wid * 2 + (lane >> 4);
            int lo = lane & 15;
            float2 val = tile[lo][hi];
            int i = hi * 256 + logrp * 16 + lo;
            obase[sigma16(i)] = val;
        }
    } else {
        float acc[16];
        #pragma unroll
        for (int q = 0; q < 16; q++) acc[q] = 0.f;
        for (int it = 0; it < 16; it++) {
            int hi = it * 16 + wid * 2 + (lane >> 4);
            int lo = lane & 15;
            float2 val = tile[lo][hi];
            int i = hi * 256 + logrp * 16 + lo;
            int j = sigma16(i);
            float p = val.x * val.x + val.y * val.y;
            #pragma unroll
            for (int q = 0; q < 16; q++) {
                unsigned sgn = ((unsigned)(j >> (15 - q)) & 1u) << 31;
                acc[q] += __int_as_float(__float_as_int(p) ^ sgn);
            }
        }
        #pragma unroll
        for (int q = 0; q < 16; q++) {
            float a = acc[q];
            #pragma unroll
            for (int o = 16; o; o >>= 1) a += __shfl_down_sync(0xffffffffu, a, o);
            if (lane == 0) wsum[wid][q] = a;
        }
        __syncthreads();
        if (tid < 16) {
            float s = 0.f;
            #pragma unroll
            for (int ww = 0; ww < 8; ww++) s += wsum[ww][tid];
            part[(b * 16 + logrp) * 16 + tid] = s;
        }
    }
}

// Final deterministic reduction of partials -> out[b][q]
__global__ __launch_bounds__(256)
void k_reduce(const float* __restrict__ part, float* __restrict__ out) {
    int idx = blockIdx.x * 256 + threadIdx.x;          // < 2048
    int b = idx >> 4, q = idx & 15;
    float s = 0.f;
    #pragma unroll
    for (int gp = 0; gp < 16; gp++) s += part[(b * 16 + gp) * 16 + q];
    out[idx] = s;
}

// ---------------------------------------------------------------------------
extern "C" void kernel_launch(void* const* d_in, const int* in_sizes, int n_in,
                              void* d_out, int out_size) {
    const float* x = (const float*)d_in[0];
    const float* w = (const float*)d_in[1];
    if (n_in >= 2 && in_sizes[0] == 192) { const float* t = x; x = w; w = t; }
    float* out = (float*)d_out;

    float2 *s0, *s1; float* part;
    cudaGetSymbolAddress((void**)&s0, g_state0);
    cudaGetSymbolAddress((void**)&s1, g_state1);
    cudaGetSymbolAddress((void**)&part, g_partial);

    k_init<<<BATCH, 256>>>(x, w, s0);

    k_low <<<dim3(32, BATCH), 256>>>(x, w, 1, s0);
    k_high<false><<<dim3(16, BATCH), 256>>>(x, w, 1, s0, s1, nullptr);

    k_low <<<dim3(32, BATCH), 256>>>(x, w, 2, s1);
    k_high<false><<<dim3(16, BATCH), 256>>>(x, w, 2, s1, s0, nullptr);

    k_low <<<dim3(32, BATCH), 256>>>(x, w, 3, s0);
    k_high<true> <<<dim3(16, BATCH), 256>>>(x, w, 3, s0, nullptr, part);

    k_reduce<<<8, 256>>>(part, out);
}

// round 6
// speedup vs baseline: 1.3391x; 1.1221x over previous
#include <cuda_runtime.h>
#include <cstdint>

#define N_QUBITS 16
#define DIM 65536
#define BATCH 128

// Scratch state buffers (device globals: allocation-free rule).
__device__ __align__(16) float4 g_state0[BATCH * DIM / 2];
__device__ __align__(16) float4 g_state1[BATCH * DIM / 2];
__device__ float g_partial[BATCH * 16 * 16];   // [b][loGroup][q]

// ---------------------------------------------------------------------------
__device__ __forceinline__ float2 cmul(float2 a, float2 b) {
    return make_float2(a.x * b.x - a.y * b.y, a.x * b.y + a.y * b.x);
}
// bit ? conj(v) : v
__device__ __forceinline__ float2 sel(float2 v, int bit) {
    return bit ? make_float2(v.x, -v.y) : v;
}

// CNOT-ring permutation sigma: new index j from old index i.
__device__ __forceinline__ int sigma16(int i) {
    int t = i;
    t ^= t >> 1; t ^= t >> 2; t ^= t >> 4; t ^= t >> 8;
    int b15 = (t ^ (i >> 15)) & 1;
    return (t & 0x7FFF) | (b15 << 15);
}

// ---------------------------------------------------------------------------
// First column of G = Rot(phi,theta,omega) @ RY(x): a=G00=(g0,g1), b=G10=(g4,g5).
__device__ void gate_col(const float* __restrict__ x,
                         const float* __restrict__ w,
                         int b, int l, int q,
                         float& g0, float& g1, float& g4, float& g5) {
    float xv  = x[(b * 4 + l) * 16 + q];
    const float* wp = w + (l * 16 + q) * 3;
    float phi = wp[0], th = wp[1], om = wp[2];
    float ct, st, cr, sr, sp, cp, sm, cm;
    sincosf(0.5f * th, &st, &ct);
    sincosf(0.5f * xv, &sr, &cr);
    sincosf(0.5f * (phi + om), &sp, &cp);
    sincosf(0.5f * (phi - om), &sm, &cm);
    float m00r =  cp * ct, m00i = -sp * ct;
    float m01r = -cm * st, m01i = -sm * st;
    float m10r =  cm * st, m10i = -sm * st;
    float m11r =  cp * ct, m11i =  sp * ct;
    g0 = m00r * cr + m01r * sr;  g1 = m00i * cr + m01i * sr;
    g4 = m10r * cr + m11r * sr;  g5 = m10i * cr + m11i * sr;
}

// G = diag(p0,conj p0) @ [[c,-s],[s,c]] @ diag(q0,conj q0)
__device__ void gate_decomp(const float* __restrict__ x,
                            const float* __restrict__ w,
                            int b, int l, int q,
                            float2& cs, float2& q0, float2& p0) {
    float g0, g1, g4, g5;
    gate_col(x, w, b, l, q, g0, g1, g4, g5);
    float ca = sqrtf(g0 * g0 + g1 * g1);
    float sb = sqrtf(g4 * g4 + g5 * g5);
    float au = atan2f(g1, g0);
    float av = atan2f(g5, g4);
    float s1, c1, s2, c2;
    sincosf(0.5f * (au + av), &s1, &c1);
    sincosf(0.5f * (au - av), &s2, &c2);
    cs = make_float2(ca, sb);
    q0 = make_float2(c1, s1);
    p0 = make_float2(c2, s2);
}

// ---------------------------------------------------------------------------
// Real butterfly network on 8 float2 amps (used by k_high):
//   lane bits 0..4 -> gcs[0..4] (shfl), reg bits -> gcs[5..7].
__device__ __forceinline__ void apply8_real(float2 v[8],
                                            const float2* __restrict__ gcs,
                                            int lane) {
    #pragma unroll
    for (int pb = 0; pb < 3; pb++) {
        int m = 1 << pb;
        float2 cp = gcs[5 + pb];
        float c = cp.x, s = cp.y;
        #pragma unroll
        for (int r = 0; r < 8; r++)
            if (!(r & m)) {
                float2 A = v[r], B = v[r + m];
                v[r]     = make_float2(c * A.x - s * B.x, c * A.y - s * B.y);
                v[r + m] = make_float2(s * A.x + c * B.x, s * A.y + c * B.y);
            }
    }
    #pragma unroll
    for (int p = 0; p < 5; p++) {
        float2 cp = gcs[p];
        float c = cp.x;
        float s = ((lane >> p) & 1) ? cp.y : -cp.y;
        #pragma unroll
        for (int r = 0; r < 8; r++) {
            float px = __shfl_xor_sync(0xffffffffu, v[r].x, 1 << p);
            float py = __shfl_xor_sync(0xffffffffu, v[r].y, 1 << p);
            v[r].x = c * v[r].x + s * px;
            v[r].y = c * v[r].y + s * py;
        }
    }
}

// ---------------------------------------------------------------------------
// K1: layer-0 product state written DIRECTLY in the sigma-permuted (j) domain.
// amp(j) = prod_p col_p(i_p) with i_p = j_p^j_{p+1} (p<=13), i_14=j_14^j_0^j_15,
// i_15=j_0^j_15  ->  amp = AL(lo,j8) * AH(hi,j0). Fully coalesced float4 writes.
__global__ __launch_bounds__(256)
void k_init(const float* __restrict__ x, const float* __restrict__ w,
            float4* __restrict__ st4) {
    int b = blockIdx.x, tid = threadIdx.x;
    __shared__ float2 colA[16][2];
    __shared__ __align__(16) float2 AL[2][256];
    __shared__ float2 AH[2][256];
    if (tid < 16) {
        float g0, g1, g4, g5;
        gate_col(x, w, b, 0, 15 - tid, g0, g1, g4, g5);
        colA[tid][0] = make_float2(g0, g1);   // bit 0 -> G00
        colA[tid][1] = make_float2(g4, g5);   // bit 1 -> G10
    }
    __syncthreads();
    {
        int m = tid;
        float2 acc = colA[0][(m ^ (m >> 1)) & 1];
        #pragma unroll
        for (int p = 1; p <= 6; p++)
            acc = cmul(acc, colA[p][((m >> p) ^ (m >> (p + 1))) & 1]);
        int m7 = (m >> 7) & 1;
        AL[0][m] = cmul(acc, colA[7][m7]);
        AL[1][m] = cmul(acc, colA[7][m7 ^ 1]);
    }
    {
        int m = tid;                           // hi bits h0..h7
        float2 acc = colA[8][(m ^ (m >> 1)) & 1];
        #pragma unroll
        for (int p = 9; p <= 13; p++)
            acc = cmul(acc, colA[p][((m >> (p - 8)) ^ (m >> (p - 7))) & 1]);
        int h6 = (m >> 6) & 1, h7 = (m >> 7) & 1;
        AH[0][m] = cmul(acc, cmul(colA[14][h6 ^ h7],     colA[15][h7]));
        AH[1][m] = cmul(acc, cmul(colA[14][h6 ^ 1 ^ h7], colA[15][1 ^ h7]));
    }
    __syncthreads();
    float4* base = st4 + (size_t)b * (DIM / 2);
    #pragma unroll 4
    for (int it = 0; it < 128; it++) {
        int j0 = it * 512 + tid * 2;
        int lo = j0 & 255, hi = j0 >> 8;
        const float2* ALs = AL[hi & 1];
        float2 a0 = cmul(AH[0][hi], ALs[lo]);
        float2 a1 = cmul(AH[1][hi], ALs[lo + 1]);
        base[it * 256 + tid] = make_float4(a0.x, a0.y, a1.x, a1.y);
    }
}

// ---------------------------------------------------------------------------
// KA: combined diagonal Dc = D2_l * (D1_{l-1} o sigma^{-1}), then real
// rotations on j-bits 0..7. float4 I/O (bit0 intra-register).
// Local amp m = r*64 + lane*2 + e: bit0=e (gate 0), bits1..5=lane (gates 1..5),
// bits6..7=r (gates 6,7).
__global__ __launch_bounds__(256)
void k_low(const float* __restrict__ x, const float* __restrict__ w,
           int layer, float4* __restrict__ st4) {
    int b = blockIdx.y, tid = threadIdx.x;
    int wid = tid >> 5, lane = tid & 31;
    __shared__ float2 gcs[8];
    __shared__ float2 q2[16], p1[16];
    __shared__ __align__(16) float2 TL[2][256];
    __shared__ float2 THs[8][2];

    if (tid < 16) {
        float2 cs, q0, p0;
        gate_decomp(x, w, b, layer, 15 - tid, cs, q0, p0);
        q2[tid] = q0;
        if (tid < 8) gcs[tid] = cs;
        if (layer > 1) {
            float2 cs2, q02, p02;
            gate_decomp(x, w, b, layer - 1, 15 - tid, cs2, q02, p02);
            p1[tid] = p02;
        } else {
            p1[tid] = make_float2(1.f, 0.f);
        }
    }
    __syncthreads();
    {   // TL(lo,b8) = prod F2_p(lo_p) (p=0..7) * prod F1_p(lo_p^lo_{p+1}) (p=0..6)
        //            * F1_7(lo_7 ^ b8)
        int m = tid;
        float2 acc = sel(q2[0], m & 1);
        #pragma unroll
        for (int p = 1; p <= 7; p++) acc = cmul(acc, sel(q2[p], (m >> p) & 1));
        #pragma unroll
        for (int p = 0; p <= 6; p++)
            acc = cmul(acc, sel(p1[p], ((m >> p) ^ (m >> (p + 1))) & 1));
        int m7 = (m >> 7) & 1;
        TL[0][m] = cmul(acc, sel(p1[7], m7));
        TL[1][m] = cmul(acc, sel(p1[7], m7 ^ 1));
    }
    if (tid < 16) {   // TH(hi,b0) per (warp, b0)
        int wi = tid >> 1, b0 = tid & 1;
        int hi = blockIdx.x * 8 + wi;
        float2 acc = sel(q2[8], hi & 1);
        #pragma unroll
        for (int p = 9; p <= 15; p++)
            acc = cmul(acc, sel(q2[p], (hi >> (p - 8)) & 1));
        #pragma unroll
        for (int p = 8; p <= 13; p++)
            acc = cmul(acc, sel(p1[p], ((hi >> (p - 8)) ^ (hi >> (p - 7))) & 1));
        int h6 = (hi >> 6) & 1, h7 = (hi >> 7) & 1;
        acc = cmul(acc, sel(p1[14], h6 ^ b0 ^ h7));
        acc = cmul(acc, sel(p1[15], b0 ^ h7));
        THs[wi][b0] = acc;
    }
    __syncthreads();

    int hi = blockIdx.x * 8 + wid;
    float2 TH0 = THs[wid][0], TH1 = THs[wid][1];
    const float4* TL4 = reinterpret_cast<const float4*>(TL[hi & 1]);
    float4* base = st4 + (size_t)b * (DIM / 2) + hi * 128;
    float4 v[4];
    #pragma unroll
    for (int r = 0; r < 4; r++) v[r] = base[r * 32 + lane];
    // combined diagonal
    #pragma unroll
    for (int r = 0; r < 4; r++) {
        float4 dd = TL4[r * 32 + lane];
        float2 d0 = cmul(TH0, make_float2(dd.x, dd.y));
        float2 d1 = cmul(TH1, make_float2(dd.z, dd.w));
        float2 A = cmul(make_float2(v[r].x, v[r].y), d0);
        float2 B = cmul(make_float2(v[r].z, v[r].w), d1);
        v[r] = make_float4(A.x, A.y, B.x, B.y);
    }
    // bit0 gate (intra-float4)
    {
        float c = gcs[0].x, s = gcs[0].y;
        #pragma unroll
        for (int r = 0; r < 4; r++) {
            float4 a = v[r];
            v[r] = make_float4(c * a.x - s * a.z, c * a.y - s * a.w,
                               s * a.x + c * a.z, s * a.y + c * a.w);
        }
    }
    // bits 1..5: lane shuffles
    #pragma unroll
    for (int p = 1; p <= 5; p++) {
        float2 cp = gcs[p];
        float c = cp.x;
        float s = ((lane >> (p - 1)) & 1) ? cp.y : -cp.y;
        int msk = 1 << (p - 1);
        #pragma unroll
        for (int r = 0; r < 4; r++) {
            float px = __shfl_xor_sync(0xffffffffu, v[r].x, msk);
            float py = __shfl_xor_sync(0xffffffffu, v[r].y, msk);
            float pz = __shfl_xor_sync(0xffffffffu, v[r].z, msk);
            float pw = __shfl_xor_sync(0xffffffffu, v[r].w, msk);
            v[r].x = c * v[r].x + s * px;
            v[r].y = c * v[r].y + s * py;
            v[r].z = c * v[r].z + s * pz;
            v[r].w = c * v[r].w + s * pw;
        }
    }
    // bits 6..7: register butterflies between r's
    #pragma unroll
    for (int pb = 0; pb < 2; pb++) {
        int m = 1 << pb;
        float2 cp = gcs[6 + pb];
        float c = cp.x, s = cp.y;
        #pragma unroll
        for (int r = 0; r < 4; r++)
            if (!(r & m)) {
                float4 A = v[r], B = v[r + m];
                v[r]     = make_float4(c * A.x - s * B.x, c * A.y - s * B.y,
                                       c * A.z - s * B.z, c * A.w - s * B.w);
                v[r + m] = make_float4(s * A.x + c * B.x, s * A.y + c * B.y,
                                       s * A.z + c * B.z, s * A.w + c * B.w);
            }
    }
    #pragma unroll
    for (int r = 0; r < 4; r++) base[r * 32 + lane] = v[r];
}

// ---------------------------------------------------------------------------
// KB: real rotations on j-bits 8..15 via smem transpose. Non-final: fused
// CNOT scatter (no diagonal -- folded into next k_low). FINAL: fused
// signed-marginal readout (no tile re-store, no per-amp 16-FMA sign pass).
template <bool FINAL>
__global__ __launch_bounds__(256)
void k_high(const float* __restrict__ x, const float* __restrict__ w,
            int layer, const float2* __restrict__ in,
            float2* __restrict__ outst, float* __restrict__ part) {
    int b = blockIdx.y, logrp = blockIdx.x;
    int tid = threadIdx.x, wid = tid >> 5, lane = tid & 31;
    __shared__ float2 gcs[8];
    __shared__ float2 tile[16][257];
    __shared__ float  warpRed[8][12];
    __shared__ float  R[12];

    if (tid < 8) {
        float2 cs, q0, p0;
        gate_decomp(x, w, b, layer, 7 - tid, cs, q0, p0);   // hi-bit p -> qubit 7-p
        gcs[tid] = cs;
    }
    __syncthreads();

    const float2* ibase = in + (size_t)b * DIM + logrp * 16;
    #pragma unroll 4
    for (int it = 0; it < 16; it++) {
        int hi = it * 16 + wid * 2 + (lane >> 4);
        int lo = lane & 15;
        tile[lo][hi] = ibase[hi * 256 + lo];
    }
    __syncthreads();

    if (!FINAL) {
        #pragma unroll
        for (int sub = 0; sub < 2; sub++) {
            int lo = wid * 2 + sub;
            float2 v[8];
            #pragma unroll
            for (int r = 0; r < 8; r++) v[r] = tile[lo][r * 32 + lane];
            apply8_real(v, gcs, lane);
            #pragma unroll
            for (int r = 0; r < 8; r++) tile[lo][r * 32 + lane] = v[r];
        }
        __syncthreads();
        float2* obase = outst + (size_t)b * DIM;
        #pragma unroll 4
        for (int it = 0; it < 16; it++) {
            int hi = it * 16 + wid * 2 + (lane >> 4);
            int lo = lane & 15;
            float2 val = tile[lo][hi];
            int i = hi * 256 + logrp * 16 + lo;
            obase[sigma16(i)] = val;
        }
    } else {
        // gates + per-(hi) lo-pair sums (sp = p0+p1, sm = p0-p1; lo4 bit0 = sub)
        float pa[8], spv[8], smv[8];
        #pragma unroll
        for (int sub = 0; sub < 2; sub++) {
            int lo = wid * 2 + sub;
            float2 v[8];
            #pragma unroll
            for (int r = 0; r < 8; r++) v[r] = tile[lo][r * 32 + lane];
            apply8_real(v, gcs, lane);
            if (sub == 0) {
                #pragma unroll
                for (int r = 0; r < 8; r++)
                    pa[r] = v[r].x * v[r].x + v[r].y * v[r].y;
            } else {
                #pragma unroll
                for (int r = 0; r < 8; r++) {
                    float pb = v[r].x * v[r].x + v[r].y * v[r].y;
                    spv[r] = pa[r] + pb;
                    smv[r] = pa[r] - pb;
                }
            }
        }
        __syncthreads();                       // everyone done reading tile
        float* S = (float*)tile;               // alias: Sp = S[0..2047], Sm = S[2048..]
        #pragma unroll
        for (int r = 0; r < 8; r++) {
            S[wid * 256 + r * 32 + lane]        = spv[r];
            S[2048 + wid * 256 + r * 32 + lane] = smv[r];
        }
        __syncthreads();

        // combine over the 8 warps (lo4 bits 1..3) -> V0..V4 for hi = tid
        float V0 = 0.f, V1 = 0.f, V2 = 0.f, V3 = 0.f, V4 = 0.f;
        #pragma unroll
        for (int w2 = 0; w2 < 8; w2++) {
            float sp = S[w2 * 256 + tid];
            float sm = S[2048 + w2 * 256 + tid];
            int pw  = __popc(w2) & 1;          // parity(lo4 bits 1..3)
            int pw2 = __popc(w2 >> 1) & 1;     // parity(lo4 bits 2..3)
            int pw3 = (w2 >> 2) & 1;           // lo4 bit 3
            V4 += sp;
            V1 += pw  ? -sp : sp;
            V2 += pw2 ? -sp : sp;
            V3 += pw3 ? -sp : sp;
            V0 += pw  ? -sm : sm;
        }
        // 12 signed hi-sums: A[0..6]=S_k (V4, suffix-parity k..7),
        // A[7..10]=SP0..SP3 (V0..V3, full parity), A[11]=S15 (V0, bits0..6)
        float A[12];
        int t = tid;
        int pf = __popc(t) & 1;
        #pragma unroll
        for (int k = 0; k < 7; k++)
            A[k] = (__popc(t >> k) & 1) ? -V4 : V4;
        A[7]  = pf ? -V0 : V0;
        A[8]  = pf ? -V1 : V1;
        A[9]  = pf ? -V2 : V2;
        A[10] = pf ? -V3 : V3;
        A[11] = (__popc(t & 0x7F) & 1) ? -V0 : V0;
        #pragma unroll
        for (int k = 0; k < 12; k++) {
            float a = A[k];
            #pragma unroll
            for (int o = 16; o; o >>= 1) a += __shfl_down_sync(0xffffffffu, a, o);
            if (lane == 0) warpRed[wid][k] = a;
        }
        __syncthreads();
        if (tid < 12) {
            float s = 0.f;
            #pragma unroll
            for (int w2 = 0; w2 < 8; w2++) s += warpRed[w2][tid];
            R[tid] = s;
        }
        __syncthreads();
        if (tid < 16) {
            int q = tid, lg = logrp;
            float sgnAll = (__popc(lg) & 1) ? -1.f : 1.f;
            float val;
            if (q == 0)        val = sgnAll * R[11];          // P=15
            else if (q < 8)    val = R[7 - q];                // P=8..14
            else if (q < 12) {                                // P=4..7
                int P = 15 - q;
                val = ((__popc(lg >> (P - 4)) & 1) ? -1.f : 1.f) * R[0];
            } else {                                          // P=0..3
                int P = 15 - q;
                val = sgnAll * R[7 + P];
            }
            part[(b * 16 + lg) * 16 + q] = val;
        }
    }
}

// Final deterministic reduction of partials -> out[b][q]
__global__ __launch_bounds__(256)
void k_reduce(const float* __restrict__ part, float* __restrict__ out) {
    int idx = blockIdx.x * 256 + threadIdx.x;          // < 2048
    int b = idx >> 4, q = idx & 15;
    float s = 0.f;
    #pragma unroll
    for (int gp = 0; gp < 16; gp++) s += part[(b * 16 + gp) * 16 + q];
    out[idx] = s;
}

// ---------------------------------------------------------------------------
extern "C" void kernel_launch(void* const* d_in, const int* in_sizes, int n_in,
                              void* d_out, int out_size) {
    const float* x = (const float*)d_in[0];
    const float* w = (const float*)d_in[1];
    if (n_in >= 2 && in_sizes[0] == 192) { const float* t = x; x = w; w = t; }
    float* out = (float*)d_out;

    float4 *s0, *s1; float* part;
    cudaGetSymbolAddress((void**)&s0, g_state0);
    cudaGetSymbolAddress((void**)&s1, g_state1);
    cudaGetSymbolAddress((void**)&part, g_partial);

    k_init<<<BATCH, 256>>>(x, w, s0);

    k_low <<<dim3(32, BATCH), 256>>>(x, w, 1, s0);
    k_high<false><<<dim3(16, BATCH), 256>>>(x, w, 1, (const float2*)s0, (float2*)s1, nullptr);

    k_low <<<dim3(32, BATCH), 256>>>(x, w, 2, s1);
    k_high<false><<<dim3(16, BATCH), 256>>>(x, w, 2, (const float2*)s1, (float2*)s0, nullptr);

    k_low <<<dim3(32, BATCH), 256>>>(x, w, 3, s0);
    k_high<true> <<<dim3(16, BATCH), 256>>>(x, w, 3, (const float2*)s0, nullptr, part);

    k_reduce<<<8, 256>>>(part, out);
}

// round 7
// speedup vs baseline: 1.5170x; 1.1329x over previous
#include <cuda_runtime.h>
#include <cstdint>

#define N_QUBITS 16
#define DIM 65536
#define BATCH 128

// Scratch state buffers (device globals: allocation-free rule).
__device__ __align__(16) float4 g_state0[BATCH * DIM / 2];
__device__ __align__(16) float4 g_state1[BATCH * DIM / 2];
__device__ float g_partial[BATCH * 16 * 16];   // [b][loGroup][q]

// Precomputed per-(batch,layer) gate data (filled by k_prep).
__device__ float2 g_cs  [BATCH * 4 * 16];          // rotation (c,s) per bit p
__device__ float2 g_TLt [BATCH * 4 * 2 * 256];     // TL[b8][lo]
__device__ float2 g_THt [BATCH * 4 * 256 * 2];     // TH[hi][b0]

// ---------------------------------------------------------------------------
__device__ __forceinline__ float2 cmul(float2 a, float2 b) {
    return make_float2(a.x * b.x - a.y * b.y, a.x * b.y + a.y * b.x);
}
// bit ? conj(v) : v
__device__ __forceinline__ float2 sel(float2 v, int bit) {
    return bit ? make_float2(v.x, -v.y) : v;
}

// CNOT-ring permutation sigma: new index j from old index i.
__device__ __forceinline__ int sigma16(int i) {
    int t = i;
    t ^= t >> 1; t ^= t >> 2; t ^= t >> 4; t ^= t >> 8;
    int b15 = (t ^ (i >> 15)) & 1;
    return (t & 0x7FFF) | (b15 << 15);
}

// ---------------------------------------------------------------------------
// First column of G = Rot(phi,theta,omega) @ RY(x): a=G00=(g0,g1), b=G10=(g4,g5).
__device__ void gate_col(const float* __restrict__ x,
                         const float* __restrict__ w,
                         int b, int l, int q,
                         float& g0, float& g1, float& g4, float& g5) {
    float xv  = x[(b * 4 + l) * 16 + q];
    const float* wp = w + (l * 16 + q) * 3;
    float phi = wp[0], th = wp[1], om = wp[2];
    float ct, st, cr, sr, sp, cp, sm, cm;
    sincosf(0.5f * th, &st, &ct);
    sincosf(0.5f * xv, &sr, &cr);
    sincosf(0.5f * (phi + om), &sp, &cp);
    sincosf(0.5f * (phi - om), &sm, &cm);
    float m00r =  cp * ct, m00i = -sp * ct;
    float m01r = -cm * st, m01i = -sm * st;
    float m10r =  cm * st, m10i = -sm * st;
    float m11r =  cp * ct, m11i =  sp * ct;
    g0 = m00r * cr + m01r * sr;  g1 = m00i * cr + m01i * sr;
    g4 = m10r * cr + m11r * sr;  g5 = m10i * cr + m11i * sr;
}

// G = diag(p0,conj p0) @ [[c,-s],[s,c]] @ diag(q0,conj q0)
__device__ void gate_decomp(const float* __restrict__ x,
                            const float* __restrict__ w,
                            int b, int l, int q,
                            float2& cs, float2& q0, float2& p0) {
    float g0, g1, g4, g5;
    gate_col(x, w, b, l, q, g0, g1, g4, g5);
    float ca = sqrtf(g0 * g0 + g1 * g1);
    float sb = sqrtf(g4 * g4 + g5 * g5);
    float au = atan2f(g1, g0);
    float av = atan2f(g5, g4);
    float s1, c1, s2, c2;
    sincosf(0.5f * (au + av), &s1, &c1);
    sincosf(0.5f * (au - av), &s2, &c2);
    cs = make_float2(ca, sb);
    q0 = make_float2(c1, s1);
    p0 = make_float2(c2, s2);
}

// ---------------------------------------------------------------------------
// K0: one block per batch element. Computes all gate decompositions for
// layers 1..3 and materializes rotation coeffs + combined diagonal tables.
__global__ __launch_bounds__(256)
void k_prep(const float* __restrict__ x, const float* __restrict__ w) {
    int b = blockIdx.x, tid = threadIdx.x;
    __shared__ float2 sq0[3][16], sp0[3][16], sid[16];
    if (tid < 48) {
        int l = tid >> 4, p = tid & 15;        // l=0..2 -> layer l+1; bit p -> qubit 15-p
        float2 cs, q0, p0;
        gate_decomp(x, w, b, l + 1, 15 - p, cs, q0, p0);
        sq0[l][p] = q0; sp0[l][p] = p0;
        g_cs[(b * 4 + l + 1) * 16 + p] = cs;
    }
    if (tid < 16) sid[tid] = make_float2(1.f, 0.f);
    __syncthreads();

    #pragma unroll
    for (int li = 0; li < 3; li++) {           // layer = li+1
        const float2* q2 = sq0[li];
        const float2* p1 = (li == 0) ? sid : sp0[li - 1];
        int base = (b * 4 + li + 1);
        {   // TL(lo=m, b8)
            int m = tid;
            float2 acc = sel(q2[0], m & 1);
            #pragma unroll
            for (int p = 1; p <= 7; p++) acc = cmul(acc, sel(q2[p], (m >> p) & 1));
            #pragma unroll
            for (int p = 0; p <= 6; p++)
                acc = cmul(acc, sel(p1[p], ((m >> p) ^ (m >> (p + 1))) & 1));
            int m7 = (m >> 7) & 1;
            g_TLt[(base * 2 + 0) * 256 + m] = cmul(acc, sel(p1[7], m7));
            g_TLt[(base * 2 + 1) * 256 + m] = cmul(acc, sel(p1[7], m7 ^ 1));
        }
        {   // TH(hi, b0)
            int hi = tid;
            float2 acc = sel(q2[8], hi & 1);
            #pragma unroll
            for (int p = 9; p <= 15; p++)
                acc = cmul(acc, sel(q2[p], (hi >> (p - 8)) & 1));
            #pragma unroll
            for (int p = 8; p <= 13; p++)
                acc = cmul(acc, sel(p1[p], ((hi >> (p - 8)) ^ (hi >> (p - 7))) & 1));
            int h6 = (hi >> 6) & 1, h7 = (hi >> 7) & 1;
            #pragma unroll
            for (int b0 = 0; b0 < 2; b0++) {
                float2 a2 = cmul(acc, sel(p1[14], h6 ^ b0 ^ h7));
                a2 = cmul(a2, sel(p1[15], b0 ^ h7));
                g_THt[(base * 256 + hi) * 2 + b0] = a2;
            }
        }
    }
}

// ---------------------------------------------------------------------------
// Real butterfly network on 8 float2 amps (used by k_high):
//   lane bits 0..4 -> gcs[0..4] (shfl), reg bits -> gcs[5..7].
__device__ __forceinline__ void apply8_real(float2 v[8],
                                            const float2* __restrict__ gcs,
                                            int lane) {
    #pragma unroll
    for (int pb = 0; pb < 3; pb++) {
        int m = 1 << pb;
        float2 cp = gcs[5 + pb];
        float c = cp.x, s = cp.y;
        #pragma unroll
        for (int r = 0; r < 8; r++)
            if (!(r & m)) {
                float2 A = v[r], B = v[r + m];
                v[r]     = make_float2(c * A.x - s * B.x, c * A.y - s * B.y);
                v[r + m] = make_float2(s * A.x + c * B.x, s * A.y + c * B.y);
            }
    }
    #pragma unroll
    for (int p = 0; p < 5; p++) {
        float2 cp = gcs[p];
        float c = cp.x;
        float s = ((lane >> p) & 1) ? cp.y : -cp.y;
        #pragma unroll
        for (int r = 0; r < 8; r++) {
            float px = __shfl_xor_sync(0xffffffffu, v[r].x, 1 << p);
            float py = __shfl_xor_sync(0xffffffffu, v[r].y, 1 << p);
            v[r].x = c * v[r].x + s * px;
            v[r].y = c * v[r].y + s * py;
        }
    }
}

// ---------------------------------------------------------------------------
// K1: layer-0 product state written DIRECTLY in the sigma-permuted (j) domain.
__global__ __launch_bounds__(256)
void k_init(const float* __restrict__ x, const float* __restrict__ w,
            float4* __restrict__ st4) {
    int b = blockIdx.x, tid = threadIdx.x;
    __shared__ float2 colA[16][2];
    __shared__ __align__(16) float2 AL[2][256];
    __shared__ float2 AH[2][256];
    if (tid < 16) {
        float g0, g1, g4, g5;
        gate_col(x, w, b, 0, 15 - tid, g0, g1, g4, g5);
        colA[tid][0] = make_float2(g0, g1);
        colA[tid][1] = make_float2(g4, g5);
    }
    __syncthreads();
    {
        int m = tid;
        float2 acc = colA[0][(m ^ (m >> 1)) & 1];
        #pragma unroll
        for (int p = 1; p <= 6; p++)
            acc = cmul(acc, colA[p][((m >> p) ^ (m >> (p + 1))) & 1]);
        int m7 = (m >> 7) & 1;
        AL[0][m] = cmul(acc, colA[7][m7]);
        AL[1][m] = cmul(acc, colA[7][m7 ^ 1]);
    }
    {
        int m = tid;
        float2 acc = colA[8][(m ^ (m >> 1)) & 1];
        #pragma unroll
        for (int p = 9; p <= 13; p++)
            acc = cmul(acc, colA[p][((m >> (p - 8)) ^ (m >> (p - 7))) & 1]);
        int h6 = (m >> 6) & 1, h7 = (m >> 7) & 1;
        AH[0][m] = cmul(acc, cmul(colA[14][h6 ^ h7],     colA[15][h7]));
        AH[1][m] = cmul(acc, cmul(colA[14][h6 ^ 1 ^ h7], colA[15][1 ^ h7]));
    }
    __syncthreads();
    float4* base = st4 + (size_t)b * (DIM / 2);
    #pragma unroll 4
    for (int it = 0; it < 128; it++) {
        int j0 = it * 512 + tid * 2;
        int lo = j0 & 255, hi = j0 >> 8;
        const float2* ALs = AL[hi & 1];
        float2 a0 = cmul(AH[0][hi], ALs[lo]);
        float2 a1 = cmul(AH[1][hi], ALs[lo + 1]);
        base[it * 256 + tid] = make_float4(a0.x, a0.y, a1.x, a1.y);
    }
}

// ---------------------------------------------------------------------------
// KA: combined diagonal (precomputed TL/TH tables) + real rotations on
// j-bits 0..7. float4 I/O (bit0 intra-register).
__global__ __launch_bounds__(256)
void k_low(int layer, float4* __restrict__ st4) {
    int b = blockIdx.y, tid = threadIdx.x;
    int wid = tid >> 5, lane = tid & 31;
    __shared__ float2 gcs[8];
    __shared__ __align__(16) float2 TL[2][256];
    __shared__ float2 THs[8][2];

    int base = b * 4 + layer;
    if (tid < 8) gcs[tid] = g_cs[base * 16 + tid];
    TL[0][tid] = g_TLt[(base * 2 + 0) * 256 + tid];
    TL[1][tid] = g_TLt[(base * 2 + 1) * 256 + tid];
    if (tid < 16) {
        int wi = tid >> 1, b0 = tid & 1;
        int hig = blockIdx.x * 8 + wi;
        THs[wi][b0] = g_THt[(base * 256 + hig) * 2 + b0];
    }
    __syncthreads();

    int hi = blockIdx.x * 8 + wid;
    float2 TH0 = THs[wid][0], TH1 = THs[wid][1];
    const float4* TL4 = reinterpret_cast<const float4*>(TL[hi & 1]);
    float4* sbase = st4 + (size_t)b * (DIM / 2) + hi * 128;
    float4 v[4];
    #pragma unroll
    for (int r = 0; r < 4; r++) v[r] = sbase[r * 32 + lane];
    // combined diagonal
    #pragma unroll
    for (int r = 0; r < 4; r++) {
        float4 dd = TL4[r * 32 + lane];
        float2 d0 = cmul(TH0, make_float2(dd.x, dd.y));
        float2 d1 = cmul(TH1, make_float2(dd.z, dd.w));
        float2 A = cmul(make_float2(v[r].x, v[r].y), d0);
        float2 B = cmul(make_float2(v[r].z, v[r].w), d1);
        v[r] = make_float4(A.x, A.y, B.x, B.y);
    }
    // bit0 gate (intra-float4)
    {
        float c = gcs[0].x, s = gcs[0].y;
        #pragma unroll
        for (int r = 0; r < 4; r++) {
            float4 a = v[r];
            v[r] = make_float4(c * a.x - s * a.z, c * a.y - s * a.w,
                               s * a.x + c * a.z, s * a.y + c * a.w);
        }
    }
    // bits 1..5: lane shuffles
    #pragma unroll
    for (int p = 1; p <= 5; p++) {
        float2 cp = gcs[p];
        float c = cp.x;
        float s = ((lane >> (p - 1)) & 1) ? cp.y : -cp.y;
        int msk = 1 << (p - 1);
        #pragma unroll
        for (int r = 0; r < 4; r++) {
            float px = __shfl_xor_sync(0xffffffffu, v[r].x, msk);
            float py = __shfl_xor_sync(0xffffffffu, v[r].y, msk);
            float pz = __shfl_xor_sync(0xffffffffu, v[r].z, msk);
            float pw = __shfl_xor_sync(0xffffffffu, v[r].w, msk);
            v[r].x = c * v[r].x + s * px;
            v[r].y = c * v[r].y + s * py;
            v[r].z = c * v[r].z + s * pz;
            v[r].w = c * v[r].w + s * pw;
        }
    }
    // bits 6..7: register butterflies
    #pragma unroll
    for (int pb = 0; pb < 2; pb++) {
        int m = 1 << pb;
        float2 cp = gcs[6 + pb];
        float c = cp.x, s = cp.y;
        #pragma unroll
        for (int r = 0; r < 4; r++)
            if (!(r & m)) {
                float4 A = v[r], B = v[r + m];
                v[r]     = make_float4(c * A.x - s * B.x, c * A.y - s * B.y,
                                       c * A.z - s * B.z, c * A.w - s * B.w);
                v[r + m] = make_float4(s * A.x + c * B.x, s * A.y + c * B.y,
                                       s * A.z + c * B.z, s * A.w + c * B.w);
            }
    }
    #pragma unroll
    for (int r = 0; r < 4; r++) sbase[r * 32 + lane] = v[r];
}

// ---------------------------------------------------------------------------
// KB: real rotations on j-bits 8..15 via smem transpose. Non-final: fused
// CNOT scatter. FINAL: fused signed-marginal readout.
template <bool FINAL>
__global__ __launch_bounds__(256)
void k_high(int layer, const float2* __restrict__ in,
            float2* __restrict__ outst, float* __restrict__ part) {
    int b = blockIdx.y, logrp = blockIdx.x;
    int tid = threadIdx.x, wid = tid >> 5, lane = tid & 31;
    __shared__ float2 gcs[8];
    __shared__ float2 tile[16][257];
    __shared__ float  warpRed[8][12];
    __shared__ float  R[12];

    if (tid < 8) gcs[tid] = g_cs[(b * 4 + layer) * 16 + 8 + tid];
    __syncthreads();

    const float2* ibase = in + (size_t)b * DIM + logrp * 16;
    #pragma unroll 4
    for (int it = 0; it < 16; it++) {
        int hi = it * 16 + wid * 2 + (lane >> 4);
        int lo = lane & 15;
        tile[lo][hi] = ibase[hi * 256 + lo];
    }
    __syncthreads();

    if (!FINAL) {
        #pragma unroll
        for (int sub = 0; sub < 2; sub++) {
            int lo = wid * 2 + sub;
            float2 v[8];
            #pragma unroll
            for (int r = 0; r < 8; r++) v[r] = tile[lo][r * 32 + lane];
            apply8_real(v, gcs, lane);
            #pragma unroll
            for (int r = 0; r < 8; r++) tile[lo][r * 32 + lane] = v[r];
        }
        __syncthreads();
        float2* obase = outst + (size_t)b * DIM;
        #pragma unroll 4
        for (int it = 0; it < 16; it++) {
            int hi = it * 16 + wid * 2 + (lane >> 4);
            int lo = lane & 15;
            float2 val = tile[lo][hi];
            int i = hi * 256 + logrp * 16 + lo;
            obase[sigma16(i)] = val;
        }
    } else {
        float pa[8], spv[8], smv[8];
        #pragma unroll
        for (int sub = 0; sub < 2; sub++) {
            int lo = wid * 2 + sub;
            float2 v[8];
            #pragma unroll
            for (int r = 0; r < 8; r++) v[r] = tile[lo][r * 32 + lane];
            apply8_real(v, gcs, lane);
            if (sub == 0) {
                #pragma unroll
                for (int r = 0; r < 8; r++)
                    pa[r] = v[r].x * v[r].x + v[r].y * v[r].y;
            } else {
                #pragma unroll
                for (int r = 0; r < 8; r++) {
                    float pb = v[r].x * v[r].x + v[r].y * v[r].y;
                    spv[r] = pa[r] + pb;
                    smv[r] = pa[r] - pb;
                }
            }
        }
        __syncthreads();
        float* S = (float*)tile;
        #pragma unroll
        for (int r = 0; r < 8; r++) {
            S[wid * 256 + r * 32 + lane]        = spv[r];
            S[2048 + wid * 256 + r * 32 + lane] = smv[r];
        }
        __syncthreads();

        float V0 = 0.f, V1 = 0.f, V2 = 0.f, V3 = 0.f, V4 = 0.f;
        #pragma unroll
        for (int w2 = 0; w2 < 8; w2++) {
            float sp = S[w2 * 256 + tid];
            float sm = S[2048 + w2 * 256 + tid];
            int pw  = __popc(w2) & 1;
            int pw2 = __popc(w2 >> 1) & 1;
            int pw3 = (w2 >> 2) & 1;
            V4 += sp;
            V1 += pw  ? -sp : sp;
            V2 += pw2 ? -sp : sp;
            V3 += pw3 ? -sp : sp;
            V0 += pw  ? -sm : sm;
        }
        float A[12];
        int t = tid;
        int pf = __popc(t) & 1;
        #pragma unroll
        for (int k = 0; k < 7; k++)
            A[k] = (__popc(t >> k) & 1) ? -V4 : V4;
        A[7]  = pf ? -V0 : V0;
        A[8]  = pf ? -V1 : V1;
        A[9]  = pf ? -V2 : V2;
        A[10] = pf ? -V3 : V3;
        A[11] = (__popc(t & 0x7F) & 1) ? -V0 : V0;
        #pragma unroll
        for (int k = 0; k < 12; k++) {
            float a = A[k];
            #pragma unroll
            for (int o = 16; o; o >>= 1) a += __shfl_down_sync(0xffffffffu, a, o);
            if (lane == 0) warpRed[wid][k] = a;
        }
        __syncthreads();
        if (tid < 12) {
            float s = 0.f;
            #pragma unroll
            for (int w2 = 0; w2 < 8; w2++) s += warpRed[w2][tid];
            R[tid] = s;
        }
        __syncthreads();
        if (tid < 16) {
            int q = tid, lg = logrp;
            float sgnAll = (__popc(lg) & 1) ? -1.f : 1.f;
            float val;
            if (q == 0)        val = sgnAll * R[11];
            else if (q < 8)    val = R[7 - q];
            else if (q < 12) {
                int P = 15 - q;
                val = ((__popc(lg >> (P - 4)) & 1) ? -1.f : 1.f) * R[0];
            } else {
                int P = 15 - q;
                val = sgnAll * R[7 + P];
            }
            part[(b * 16 + lg) * 16 + q] = val;
        }
    }
}

// Final deterministic reduction of partials -> out[b][q]
__global__ __launch_bounds__(256)
void k_reduce(const float* __restrict__ part, float* __restrict__ out) {
    int idx = blockIdx.x * 256 + threadIdx.x;
    int b = idx >> 4, q = idx & 15;
    float s = 0.f;
    #pragma unroll
    for (int gp = 0; gp < 16; gp++) s += part[(b * 16 + gp) * 16 + q];
    out[idx] = s;
}

// ---------------------------------------------------------------------------
extern "C" void kernel_launch(void* const* d_in, const int* in_sizes, int n_in,
                              void* d_out, int out_size) {
    const float* x = (const float*)d_in[0];
    const float* w = (const float*)d_in[1];
    if (n_in >= 2 && in_sizes[0] == 192) { const float* t = x; x = w; w = t; }
    float* out = (float*)d_out;

    float4 *s0, *s1; float* part;
    cudaGetSymbolAddress((void**)&s0, g_state0);
    cudaGetSymbolAddress((void**)&s1, g_state1);
    cudaGetSymbolAddress((void**)&part, g_partial);

    k_prep<<<BATCH, 256>>>(x, w);
    k_init<<<BATCH, 256>>>(x, w, s0);

    k_low <<<dim3(32, BATCH), 256>>>(1, s0);
    k_high<false><<<dim3(16, BATCH), 256>>>(1, (const float2*)s0, (float2*)s1, nullptr);

    k_low <<<dim3(32, BATCH), 256>>>(2, s1);
    k_high<false><<<dim3(16, BATCH), 256>>>(2, (const float2*)s1, (float2*)s0, nullptr);

    k_low <<<dim3(32, BATCH), 256>>>(3, s0);
    k_high<true> <<<dim3(16, BATCH), 256>>>(3, (const float2*)s0, nullptr, part);

    k_reduce<<<8, 256>>>(part, out);
}